// round 12
// baseline (speedup 1.0000x reference)
#include <cuda_runtime.h>
#include <cstdint>

#define BB 256
#define TT 199
#define QQ 1000
#define NROW (BB * TT)               // 50,944
#define NEL  ((size_t)NROW * QQ)     // 50,944,000

// Per-batch accumulators (fire-and-forget REDG from row blocks; read, used
// and reset by final_kernel — kernel boundary provides all ordering).
__device__ double g_bsum[BB];
__device__ int    g_bcnt[BB];

// 512 threads per block; half h (threads h*256..h*256+255) processes row
// t = 2*blockIdx.x + h of batch blockIdx.y. Per-thread work is identical to
// the proven 82%-DRAM body; only block grouping changed (half the blocks).
__global__ __launch_bounds__(512) void row_kernel(
    const float* __restrict__ pred,    // (B, T, Q)
    const float* __restrict__ batch,   // (B, T+1, Q)
    float* __restrict__ out)
{
    const int b    = blockIdx.y;
    const int tid  = threadIdx.x;
    const int half = tid >> 8;           // 0 or 1
    const int htid = tid & 255;          // thread index within half
    const int lane = tid & 31;
    const int wid  = tid >> 5;           // 0..15
    const int t    = 2 * blockIdx.x + half;
    const bool active = (t < TT);        // half B of last block is idle

    const size_t row = (size_t)b * TT + t;
    const float* __restrict__ gt_row = batch + ((size_t)b * (TT + 1) + (t + 1)) * QQ;
    const float* __restrict__ p_row  = pred + row * QQ;

    __shared__ int   s_w[16];
    __shared__ float s_red[16];

    // ---- all 8 loads up front, unconditionally (max MLP) ----
    float g[4], p[4];
    #pragma unroll
    for (int k = 0; k < 4; k++) {
        int q = htid + 256 * k;
        bool valid = active && ((k < 3) || (htid < QQ - 768));   // q < 1000
        g[k] = valid ? gt_row[q] : 0.0f;
        p[k] = valid ? p_row[q]  : 0.0f;
    }

    // ---- per-half any(g == 1) ----
    int anyv = (g[0] == 1.0f) | (g[1] == 1.0f) | (g[2] == 1.0f) | (g[3] == 1.0f);
    unsigned wany = __ballot_sync(0xFFFFFFFFu, anyv);
    if (lane == 0) s_w[wid] = (wany != 0);
    __syncthreads();
    const int base8 = half * 8;
    const int masked = s_w[base8+0] | s_w[base8+1] | s_w[base8+2] | s_w[base8+3] |
                       s_w[base8+4] | s_w[base8+5] | s_w[base8+6] | s_w[base8+7];
    const float fm = masked ? 1.0f : 0.0f;

    float* __restrict__ out_pred = out + 1 + row * QQ;
    float* __restrict__ out_gt   = out + 1 + NEL + row * QQ;

    float lsum = 0.0f;   // +(g*log p + (1-g)*log(1-p)); bce = -lsum
    #pragma unroll
    for (int k = 0; k < 4; k++) {
        int q = htid + 256 * k;
        bool valid = active && ((k < 3) || (htid < QQ - 768));
        float pp = p[k], gg = g[k];
        float lp = fmaxf(__logf(pp),        -100.0f);
        float l1 = fmaxf(__logf(1.0f - pp), -100.0f);
        lsum += gg * lp + (1.0f - gg) * l1;
        if (valid) {
            out_pred[q] = pp * fm;
            out_gt[q]   = gg * fm;
        }
    }

    // ---- per-half reduction of lsum ----
    #pragma unroll
    for (int off = 16; off > 0; off >>= 1)
        lsum += __shfl_down_sync(0xFFFFFFFFu, lsum, off);
    if (lane == 0) s_red[wid] = lsum;
    __syncthreads();

    // Warp 0 finalizes half A; warp 8 finalizes half B.
    if ((wid == 0 || wid == 8) && active) {
        float v = (lane < 8) ? s_red[base8 + lane] : 0.0f;
        #pragma unroll
        for (int off = 4; off > 0; off >>= 1)
            v += __shfl_down_sync(0xFFFFFFFFu, v, off);
        if (lane == 0) {
            out[1 + 2 * NEL + row] = fm;   // row_mask as float 0/1
            if (masked) {
                atomicAdd(&g_bsum[b], (double)(-v));   // fire-and-forget REDG
                atomicAdd(&g_bcnt[b], 1);
            }
        }
    }
}

// ===== Tiny finalize: 1 block, 256 threads. Thread b handles batch b. =====
__global__ __launch_bounds__(256) void final_kernel(float* __restrict__ out)
{
    const int b    = threadIdx.x;
    const int lane = b & 31;
    const int w    = b >> 5;

    __shared__ double s_d[8];

    const int    c = g_bcnt[b];
    const double s = g_bsum[b];
    double v = (c > 0) ? (s / ((double)c * (double)QQ)) : 0.0;

    // reset for next graph replay (deterministic)
    g_bsum[b] = 0.0;
    g_bcnt[b] = 0;

    #pragma unroll
    for (int off = 16; off > 0; off >>= 1)
        v += __shfl_down_sync(0xFFFFFFFFu, v, off);
    if (lane == 0) s_d[w] = v;
    __syncthreads();
    if (b < 8) {
        double x = s_d[b];
        #pragma unroll
        for (int off = 4; off > 0; off >>= 1)
            x += __shfl_down_sync(0xFFu, x, off);
        if (b == 0) out[0] = (float)x;
    }
}

extern "C" void kernel_launch(void* const* d_in, const int* in_sizes, int n_in,
                              void* d_out, int out_size) {
    const float* pred  = (const float*)d_in[0];
    const float* batch = (const float*)d_in[1];
    float* out = (float*)d_out;

    dim3 grid((TT + 1) / 2, BB);       // 100 x 256 blocks, 512 threads
    row_kernel<<<grid, 512>>>(pred, batch, out);
    final_kernel<<<1, 256>>>(out);
}

// round 13
// speedup vs baseline: 1.0432x; 1.0432x over previous
#include <cuda_runtime.h>
#include <cstdint>

#define BB 256
#define TT 199
#define QQ 1000
#define NROW (BB * TT)               // 50,944
#define NEL  ((size_t)NROW * QQ)     // 50,944,000

// Scratch (__device__ global, no allocation)
__device__ float g_rowbce[NROW];

// ===== Proven hot-path kernel (117.5us, DRAM 82.1%) — body identical except
// streaming cache hints on the once-touched bulk data, + PDL trigger. =====
__global__ __launch_bounds__(256) void row_kernel(
    const float* __restrict__ pred,    // (B, T, Q)
    const float* __restrict__ batch,   // (B, T+1, Q)
    float* __restrict__ out)
{
    const int t   = blockIdx.x;
    const int b   = blockIdx.y;
    const int tid = threadIdx.x;
    const int lane = tid & 31;
    const int wid  = tid >> 5;

    const size_t row = (size_t)b * TT + t;
    const float* __restrict__ gt_row = batch + ((size_t)b * (TT + 1) + (t + 1)) * QQ;
    const float* __restrict__ p_row  = pred + row * QQ;

    __shared__ int   s_w[8];
    __shared__ float s_red[8];

    // ---- all 8 loads up front, unconditionally (max MLP); streaming hint:
    // inputs are touched exactly once, keep them evict-first in L2. ----
    float g[4], p[4];
    #pragma unroll
    for (int k = 0; k < 4; k++) {
        int q = tid + 256 * k;
        bool valid = (k < 3) || (tid < QQ - 768);   // q < 1000
        g[k] = valid ? __ldcs(gt_row + q) : 0.0f;
        p[k] = valid ? __ldcs(p_row + q)  : 0.0f;
    }

    // ---- block-wide any(g == 1) ----
    int anyv = (g[0] == 1.0f) | (g[1] == 1.0f) | (g[2] == 1.0f) | (g[3] == 1.0f);
    unsigned wany = __ballot_sync(0xFFFFFFFFu, anyv);
    if (lane == 0) s_w[wid] = (wany != 0);
    __syncthreads();
    const int masked = s_w[0] | s_w[1] | s_w[2] | s_w[3] |
                       s_w[4] | s_w[5] | s_w[6] | s_w[7];
    const float fm = masked ? 1.0f : 0.0f;

    float* __restrict__ out_pred = out + 1 + row * QQ;
    float* __restrict__ out_gt   = out + 1 + NEL + row * QQ;

    float lsum = 0.0f;   // +(g*log p + (1-g)*log(1-p)); bce = -lsum
    #pragma unroll
    for (int k = 0; k < 4; k++) {
        int q = tid + 256 * k;
        bool valid = (k < 3) || (tid < QQ - 768);
        float pp = p[k], gg = g[k];
        float lp = fmaxf(__logf(pp),        -100.0f);
        float l1 = fmaxf(__logf(1.0f - pp), -100.0f);
        lsum += gg * lp + (1.0f - gg) * l1;
        if (valid) {
            // streaming stores: written once, never re-read — don't pollute L2
            __stcs(out_pred + q, pp * fm);
            __stcs(out_gt + q,   gg * fm);
        }
    }

    // ---- block reduction of lsum ----
    #pragma unroll
    for (int off = 16; off > 0; off >>= 1)
        lsum += __shfl_down_sync(0xFFFFFFFFu, lsum, off);
    if (lane == 0) s_red[wid] = lsum;
    __syncthreads();
    if (tid < 32) {
        float v = (tid < 8) ? s_red[tid] : 0.0f;
        #pragma unroll
        for (int off = 4; off > 0; off >>= 1)
            v += __shfl_down_sync(0xFFFFFFFFu, v, off);
        if (tid == 0) {
            g_rowbce[row] = fm * (-v);         // re-read by finalize: default policy
            out[1 + 2 * NEL + row] = fm;       // row_mask as float 0/1
        }
    } else if (tid == 255 && t == 0 && b == 0) {
        out[0] = 0.0f;                         // base for finalize atomics
    }

    // PDL: allow the dependent finalize grid to begin launching now.
    cudaTriggerProgrammaticLaunchCompletion();
}

// ===== Parallel finalize: one block per batch (256 blocks, 224 thr). =====
__global__ __launch_bounds__(224) void final_kernel(float* __restrict__ out)
{
    const int b    = blockIdx.x;
    const int tid  = threadIdx.x;
    const int lane = tid & 31;
    const int w    = tid >> 5;

    __shared__ float s_s[7];
    __shared__ int   s_c[7];

    cudaGridDependencySynchronize();   // wait for row_kernel completion

    float v = 0.0f;
    int   c = 0;
    if (tid < TT) {
        v = g_rowbce[b * TT + tid];
        c = (v != 0.0f);   // masked row => bce >= ~10; unmasked => exactly 0
    }
    #pragma unroll
    for (int off = 16; off > 0; off >>= 1) {
        v += __shfl_down_sync(0xFFFFFFFFu, v, off);
        c += __shfl_down_sync(0xFFFFFFFFu, c, off);
    }
    if (lane == 0) { s_s[w] = v; s_c[w] = c; }
    __syncthreads();
    if (tid == 0) {
        float sum = 0.0f; int cnt = 0;
        #pragma unroll
        for (int i = 0; i < 7; i++) { sum += s_s[i]; cnt += s_c[i]; }
        if (cnt > 0)
            atomicAdd(out, (float)((double)sum / ((double)cnt * (double)QQ)));
    }
}

extern "C" void kernel_launch(void* const* d_in, const int* in_sizes, int n_in,
                              void* d_out, int out_size) {
    const float* pred  = (const float*)d_in[0];
    const float* batch = (const float*)d_in[1];
    float* out = (float*)d_out;

    dim3 grid(TT, BB);
    row_kernel<<<grid, 256>>>(pred, batch, out);

    // Finalize with programmatic dependent launch.
    cudaLaunchConfig_t cfg = {};
    cfg.gridDim  = dim3(BB, 1, 1);
    cfg.blockDim = dim3(224, 1, 1);
    cfg.dynamicSmemBytes = 0;
    cfg.stream = 0;
    cudaLaunchAttribute attr[1];
    attr[0].id = cudaLaunchAttributeProgrammaticStreamSerialization;
    attr[0].val.programmaticStreamSerializationAllowed = 1;
    cfg.attrs = attr;
    cfg.numAttrs = 1;
    cudaLaunchKernelEx(&cfg, final_kernel, out);
}

// round 14
// speedup vs baseline: 1.0563x; 1.0125x over previous
#include <cuda_runtime.h>
#include <cstdint>

#define BB 256
#define TT 199
#define QQ 1000
#define NROW (BB * TT)               // 50,944
#define NEL  ((size_t)NROW * QQ)     // 50,944,000

// One packed accumulator per batch:
//   bits[63:56] arrival count (== TT when batch complete)
//   bits[55:48] masked-row count
//   bits[47:0]  bce sum, fixed-point * 2^20 (max ~2.1e13 < 2^48)
// Written only via atomicAdd (fire-and-forget) by row blocks; consumed and
// reset by final_kernel. No fences needed: the packed word is simultaneously
// the data and the completion counter (same-address atomic serialization).
__device__ unsigned long long g_pack[BB];

// ===== Proven hot-path body (117.5us, DRAM 82.1%) — unchanged except the
// epilogue REDG and an early PDL trigger. =====
__global__ __launch_bounds__(256) void row_kernel(
    const float* __restrict__ pred,    // (B, T, Q)
    const float* __restrict__ batch,   // (B, T+1, Q)
    float* __restrict__ out)
{
    const int t   = blockIdx.x;
    const int b   = blockIdx.y;
    const int tid = threadIdx.x;
    const int lane = tid & 31;
    const int wid  = tid >> 5;

    const size_t row = (size_t)b * TT + t;
    const float* __restrict__ gt_row = batch + ((size_t)b * (TT + 1) + (t + 1)) * QQ;
    const float* __restrict__ p_row  = pred + row * QQ;

    __shared__ int   s_w[8];
    __shared__ float s_red[8];

    // ---- all 8 loads up front, unconditionally (max MLP) ----
    float g[4], p[4];
    #pragma unroll
    for (int k = 0; k < 4; k++) {
        int q = tid + 256 * k;
        bool valid = (k < 3) || (tid < QQ - 768);   // q < 1000
        g[k] = valid ? gt_row[q] : 0.0f;
        p[k] = valid ? p_row[q]  : 0.0f;
    }

    // ---- block-wide any(g == 1) ----
    int anyv = (g[0] == 1.0f) | (g[1] == 1.0f) | (g[2] == 1.0f) | (g[3] == 1.0f);
    unsigned wany = __ballot_sync(0xFFFFFFFFu, anyv);
    if (lane == 0) s_w[wid] = (wany != 0);
    __syncthreads();
    const int masked = s_w[0] | s_w[1] | s_w[2] | s_w[3] |
                       s_w[4] | s_w[5] | s_w[6] | s_w[7];
    const float fm = masked ? 1.0f : 0.0f;

    // Early PDL trigger: let the (tiny, spinning) finalize grid launch while
    // this grid is still running. Correctness does not depend on timing.
    cudaTriggerProgrammaticLaunchCompletion();

    float* __restrict__ out_pred = out + 1 + row * QQ;
    float* __restrict__ out_gt   = out + 1 + NEL + row * QQ;

    float lsum = 0.0f;   // +(g*log p + (1-g)*log(1-p)); bce = -lsum
    #pragma unroll
    for (int k = 0; k < 4; k++) {
        int q = tid + 256 * k;
        bool valid = (k < 3) || (tid < QQ - 768);
        float pp = p[k], gg = g[k];
        float lp = fmaxf(__logf(pp),        -100.0f);
        float l1 = fmaxf(__logf(1.0f - pp), -100.0f);
        lsum += gg * lp + (1.0f - gg) * l1;
        if (valid) {
            out_pred[q] = pp * fm;
            out_gt[q]   = gg * fm;
        }
    }

    // ---- block reduction of lsum ----
    #pragma unroll
    for (int off = 16; off > 0; off >>= 1)
        lsum += __shfl_down_sync(0xFFFFFFFFu, lsum, off);
    if (lane == 0) s_red[wid] = lsum;
    __syncthreads();
    if (tid < 32) {
        float v = (tid < 8) ? s_red[tid] : 0.0f;
        #pragma unroll
        for (int off = 4; off > 0; off >>= 1)
            v += __shfl_down_sync(0xFFFFFFFFu, v, off);
        if (tid == 0) {
            out[1 + 2 * NEL + row] = fm;   // row_mask as float 0/1
            const double bce = (double)(fm * (-v));   // >= 0
            unsigned long long contrib =
                (1ull << 56)
                | (masked ? (1ull << 48) : 0ull)
                | (unsigned long long)(bce * 1048576.0 + 0.5);   // 2^20
            atomicAdd(&g_pack[b], contrib);   // fire-and-forget REDG
        }
    }
}

// ===== Spin-finalize: ONE block, 256 threads; thread b owns batch b.
// Polls the packed word with a zero-add RMW (serialized with writers, so a
// read showing arrivals==TT contains the complete batch data). =====
__global__ __launch_bounds__(256) void final_kernel(float* __restrict__ out)
{
    const int b    = threadIdx.x;
    const int lane = b & 31;
    const int w    = b >> 5;

    __shared__ double s_d[8];

    unsigned long long v = atomicAdd(&g_pack[b], 0ull);
    while ((v >> 56) != (unsigned long long)TT) {
        __nanosleep(200);
        v = atomicAdd(&g_pack[b], 0ull);
    }
    g_pack[b] = 0ull;   // reset for next graph replay (only thread b touches it)

    const unsigned cnt = (unsigned)((v >> 48) & 0xFFull);
    const double  sum  = (double)(v & 0xFFFFFFFFFFFFull) * (1.0 / 1048576.0);
    double part = (cnt > 0) ? sum / ((double)cnt * (double)QQ) : 0.0;

    #pragma unroll
    for (int off = 16; off > 0; off >>= 1)
        part += __shfl_down_sync(0xFFFFFFFFu, part, off);
    if (lane == 0) s_d[w] = part;
    __syncthreads();
    if (b < 8) {
        double x = s_d[b];
        #pragma unroll
        for (int off = 4; off > 0; off >>= 1)
            x += __shfl_down_sync(0xFFu, x, off);
        if (b == 0) out[0] = (float)x;
    }
}

extern "C" void kernel_launch(void* const* d_in, const int* in_sizes, int n_in,
                              void* d_out, int out_size) {
    const float* pred  = (const float*)d_in[0];
    const float* batch = (const float*)d_in[1];
    float* out = (float*)d_out;

    dim3 grid(TT, BB);
    row_kernel<<<grid, 256>>>(pred, batch, out);

    // PDL launch: finalize may start while row_kernel is still running; it
    // synchronizes via the packed atomics, not via grid completion.
    cudaLaunchConfig_t cfg = {};
    cfg.gridDim  = dim3(1, 1, 1);
    cfg.blockDim = dim3(256, 1, 1);
    cfg.dynamicSmemBytes = 0;
    cfg.stream = 0;
    cudaLaunchAttribute attr[1];
    attr[0].id = cudaLaunchAttributeProgrammaticStreamSerialization;
    attr[0].val.programmaticStreamSerializationAllowed = 1;
    cfg.attrs = attr;
    cfg.numAttrs = 1;
    cudaLaunchKernelEx(&cfg, final_kernel, out);
}